// round 9
// baseline (speedup 1.0000x reference)
#include <cuda_runtime.h>
#include <math.h>

#define BATCH 256
#define SEQ   512
#define ISZ   256
#define HSZ   512
#define G4    2048   // 4*HSZ gate-interleaved: col j = u*4 + g, g in {i,f,g,o}

typedef unsigned long long ull;

// ---------------- device scratch (allocation-free) ----------------
__device__ float g_xu[(size_t)SEQ * BATCH * G4];  // xu[t][b][j]
__device__ float g_h[2][BATCH * HSZ];             // double-buffered hidden state
__device__ unsigned g_arr[128];                   // 4 group barriers, 128B apart

// ---------------- f32x2 helpers ----------------
__device__ __forceinline__ ull fma2(ull a, ull b, ull c) {
    ull d;
    asm("fma.rn.f32x2 %0, %1, %2, %3;" : "=l"(d) : "l"(a), "l"(b), "l"(c));
    return d;
}
__device__ __forceinline__ ull dup2(float x) {
    ull d;
    asm("mov.b64 %0, {%1, %1};" : "=l"(d) : "f"(x));
    return d;
}
__device__ __forceinline__ float2 unpk(ull v) {
    float2 r;
    asm("mov.b64 {%0, %1}, %2;" : "=f"(r.x), "=f"(r.y) : "l"(v));
    return r;
}
__device__ __forceinline__ float fsig(float x)  { return 1.0f / (1.0f + __expf(-x)); }
__device__ __forceinline__ float ftanh(float x) { return 2.0f / (1.0f + __expf(-2.0f * x)) - 1.0f; }

__device__ __forceinline__ void arrive_release(unsigned* p) {
    asm volatile("red.release.gpu.global.add.u32 [%0], 1;" :: "l"(p) : "memory");
}
__device__ __forceinline__ unsigned poll_acquire(const unsigned* p) {
    unsigned v;
    asm volatile("ld.acquire.gpu.global.u32 %0, [%1];" : "=r"(v) : "l"(p) : "memory");
    return v;
}

// ============ phase 1: xu = x @ Wu (interleaved on the fly) + bias ==========
#define XBM 64
#define XBN 64
#define XBK 16
#define XAS 34

__global__ __launch_bounds__(256) void xu_kernel(
    const float* __restrict__ x,
    const float* __restrict__ Wui, const float* __restrict__ Wuf,
    const float* __restrict__ Wug, const float* __restrict__ Wuo,
    const float* __restrict__ bi,  const float* __restrict__ bf,
    const float* __restrict__ bg,  const float* __restrict__ bo) {
    __shared__ float As[XBM * XAS];
    __shared__ float Bs[XBK * XBN];

    if (blockIdx.x == 0 && blockIdx.y == 0 && threadIdx.x < 4)
        g_arr[threadIdx.x * 32] = 0u;

    int m0 = blockIdx.y * XBM;
    int n0 = blockIdx.x * XBN;
    int tid = threadIdx.x;
    int tx = tid & 15;
    int ty = tid >> 4;

    int prow = tid >> 2;
    int pkof = (tid & 3) * 4;
    int brow = tid >> 4;
    int bu   = tid & 15;

    int m = m0 + prow;
    int t = m >> 8;
    int b = m & 255;
    const float* aptr = x + (size_t)b * (SEQ * ISZ) + (size_t)t * ISZ + pkof;
    int ubase = (n0 >> 2) + bu;

    ull acc[4][2] = {};

    for (int k0 = 0; k0 < ISZ; k0 += XBK) {
        float4 av = *(const float4*)(aptr + k0);
        *(float2*)&As[prow * XAS + 2 * (pkof + 0)] = make_float2(av.x, av.x);
        *(float2*)&As[prow * XAS + 2 * (pkof + 1)] = make_float2(av.y, av.y);
        *(float2*)&As[prow * XAS + 2 * (pkof + 2)] = make_float2(av.z, av.z);
        *(float2*)&As[prow * XAS + 2 * (pkof + 3)] = make_float2(av.w, av.w);
        int kr = (k0 + brow) * HSZ + ubase;
        Bs[brow * XBN + bu * 4 + 0] = Wui[kr];
        Bs[brow * XBN + bu * 4 + 1] = Wuf[kr];
        Bs[brow * XBN + bu * 4 + 2] = Wug[kr];
        Bs[brow * XBN + bu * 4 + 3] = Wuo[kr];
        __syncthreads();

#pragma unroll
        for (int kk = 0; kk < XBK; kk++) {
            ulonglong2 b2 = *(const ulonglong2*)&Bs[kk * XBN + tx * 4];
#pragma unroll
            for (int r = 0; r < 4; r++) {
                ull a2 = *(const ull*)&As[(ty * 4 + r) * XAS + 2 * kk];
                acc[r][0] = fma2(a2, b2.x, acc[r][0]);
                acc[r][1] = fma2(a2, b2.y, acc[r][1]);
            }
        }
        __syncthreads();
    }

    int u = (n0 >> 2) + tx;
    float4 bias = {bi[u], bf[u], bg[u], bo[u]};
#pragma unroll
    for (int r = 0; r < 4; r++) {
        float2 lo = unpk(acc[r][0]);
        float2 hi = unpk(acc[r][1]);
        float4 ov = {lo.x + bias.x, lo.y + bias.y, hi.x + bias.z, hi.y + bias.w};
        *(float4*)(g_xu + (size_t)(m0 + ty * 4 + r) * G4 + n0 + tx * 4) = ov;
    }
}

// ============ phase 2: PERSISTENT, all 512 steps =============================
// 128 blocks = 4 batch-groups x 32 col-tiles; tile 64 batch x 64 cols.
// 512 threads: lane-packed K-quarters (q = tid&3), 8x4 microtile per thread.
// Cross-quarter reduce via shfl butterfly (no EP smem). Conflict-free XOR
// swizzle on staged h. Per-group (32-block) grid barriers.
#define PBLKS 128
#define PM 64
#define PN 64
#define QK 128          // K per quarter
#define CH 16           // k per staged chunk
#define NCH 8
#define ABST 1024       // words per (q, pingpong) staging buffer (16 x 64)
#define WHS_F (HSZ * PN)              // 32768
#define P_SMEM_BYTES ((WHS_F + 8 * ABST) * 4)   // 163840 B

extern __shared__ float s_mem[];

__global__ __launch_bounds__(512, 1) void lstm_persistent(
    float* __restrict__ out,
    const float* __restrict__ Whi, const float* __restrict__ Whf,
    const float* __restrict__ Whg, const float* __restrict__ Who) {
    float* Whs  = s_mem;                   // [512][64] gate-interleaved slice
    float* Abuf = s_mem + WHS_F;           // [4 q][2 pp][16 k][64 swizzled]

    int tid = threadIdx.x;
    int n0 = (blockIdx.x & 31) * PN;       // col tile
    int by = blockIdx.x >> 5;              // batch group 0..3
    int b0 = by * PM;

    int q   = tid & 3;                     // K-quarter (lane-packed)
    int tx  = (tid >> 2) & 15;             // col-quad (unit)
    int ty8 = (tid >> 6) * 8;              // row-oct base
    int mq  = q * 8;                       // swizzle contribution of q

    // staging mapping: thread stages for its own quarter
    int j    = tid >> 2;                   // 0..127
    int srow = j >> 1;                     // 0..63
    int skh  = (j & 1) * 8;                // 0 or 8
    int scol = srow ^ mq ^ ((skh & 8) ? 4 : 0);   // constant per thread

    unsigned* bar = &g_arr[by * 32];

    // ---- stage W_h slice (gate-interleaved on the fly), once ----
    for (int idx = tid; idx < WHS_F; idx += 512) {
        int k = idx >> 6, c = idx & 63;
        int u = (n0 >> 2) + (c >> 2), gg = c & 3;
        const float* W = (gg == 0) ? Whi : (gg == 1) ? Whf : (gg == 2) ? Whg : Who;
        Whs[idx] = W[k * HSZ + u];
    }
    __syncthreads();

    float cA = 0.0f, cB = 0.0f;            // cell state: rows ty8+2q, +1; unit u
    float* AbQ = Abuf + q * (2 * ABST);
    int rowA = ty8 + 2 * q;
    int u0 = (n0 >> 2) + tx;
    int tx4 = tx * 4;

    for (int t = 0; t < SEQ; t++) {
        const float* __restrict__ h_in = g_h[t & 1];
        float* __restrict__ h_out = (t == SEQ - 1) ? out : g_h[(t + 1) & 1];

        // prefetch xu gates for this thread's two cells
        const float* xp = g_xu + ((size_t)t * BATCH + b0 + rowA) * G4 + n0 + tx4;
        float4 xvA = __ldcg((const float4*)xp);
        float4 xvB = __ldcg((const float4*)(xp + G4));

        ull acc[4][4];
#pragma unroll
        for (int i = 0; i < 4; i++)
#pragma unroll
            for (int jj = 0; jj < 4; jj++) acc[i][jj] = 0ull;

        if (t > 0) {
            const float* aptr = h_in + (size_t)(b0 + srow) * HSZ + q * QK + skh;
            float4 pa = __ldcg((const float4*)aptr);
            float4 pb = __ldcg((const float4*)(aptr + 4));

            // store chunk 0 (swizzled, conflict-free)
            {
                float* B0 = AbQ;
                B0[(skh + 0) * 64 + scol] = pa.x;
                B0[(skh + 1) * 64 + scol] = pa.y;
                B0[(skh + 2) * 64 + scol] = pa.z;
                B0[(skh + 3) * 64 + scol] = pa.w;
                B0[(skh + 4) * 64 + scol] = pb.x;
                B0[(skh + 5) * 64 + scol] = pb.y;
                B0[(skh + 6) * 64 + scol] = pb.z;
                B0[(skh + 7) * 64 + scol] = pb.w;
            }
            __syncthreads();

            for (int s = 0; s < NCH; s++) {
                if (s < NCH - 1) {
                    pa = __ldcg((const float4*)(aptr + (s + 1) * CH));
                    pb = __ldcg((const float4*)(aptr + (s + 1) * CH + 4));
                }

                const float* Ac = AbQ + (s & 1) * ABST;
                const float* WR = Whs + (size_t)(q * QK + s * CH) * PN + tx4;
#pragma unroll
                for (int kk = 0; kk < CH; kk++) {
                    int c0 = ty8 ^ mq ^ ((kk & 8) ? 4 : 0);
                    ulonglong2 aA = *(const ulonglong2*)&Ac[kk * 64 + c0];
                    ulonglong2 aB = *(const ulonglong2*)&Ac[kk * 64 + (c0 ^ 4)];
                    float4 b4 = *(const float4*)(WR + kk * PN);
                    ull bd0 = dup2(b4.x), bd1 = dup2(b4.y);
                    ull bd2 = dup2(b4.z), bd3 = dup2(b4.w);
                    acc[0][0] = fma2(aA.x, bd0, acc[0][0]);
                    acc[1][0] = fma2(aA.y, bd0, acc[1][0]);
                    acc[2][0] = fma2(aB.x, bd0, acc[2][0]);
                    acc[3][0] = fma2(aB.y, bd0, acc[3][0]);
                    acc[0][1] = fma2(aA.x, bd1, acc[0][1]);
                    acc[1][1] = fma2(aA.y, bd1, acc[1][1]);
                    acc[2][1] = fma2(aB.x, bd1, acc[2][1]);
                    acc[3][1] = fma2(aB.y, bd1, acc[3][1]);
                    acc[0][2] = fma2(aA.x, bd2, acc[0][2]);
                    acc[1][2] = fma2(aA.y, bd2, acc[1][2]);
                    acc[2][2] = fma2(aB.x, bd2, acc[2][2]);
                    acc[3][2] = fma2(aB.y, bd2, acc[3][2]);
                    acc[0][3] = fma2(aA.x, bd3, acc[0][3]);
                    acc[1][3] = fma2(aA.y, bd3, acc[1][3]);
                    acc[2][3] = fma2(aB.x, bd3, acc[2][3]);
                    acc[3][3] = fma2(aB.y, bd3, acc[3][3]);
                }

                if (s < NCH - 1) {
                    float* Bn = AbQ + ((s + 1) & 1) * ABST;
                    Bn[(skh + 0) * 64 + scol] = pa.x;
                    Bn[(skh + 1) * 64 + scol] = pa.y;
                    Bn[(skh + 2) * 64 + scol] = pa.z;
                    Bn[(skh + 3) * 64 + scol] = pa.w;
                    Bn[(skh + 4) * 64 + scol] = pb.x;
                    Bn[(skh + 5) * 64 + scol] = pb.y;
                    Bn[(skh + 6) * 64 + scol] = pb.z;
                    Bn[(skh + 7) * 64 + scol] = pb.w;
                }
                __syncthreads();
            }
        }

        // ---- cross-quarter reduce: shfl butterfly over lanes l^1, l^2 ----
        float sv[4][4][2];
#pragma unroll
        for (int rp = 0; rp < 4; rp++)
#pragma unroll
            for (int c = 0; c < 4; c++) {
                float2 f = unpk(acc[rp][c]);
                f.x += __shfl_xor_sync(0xffffffffu, f.x, 1);
                f.y += __shfl_xor_sync(0xffffffffu, f.y, 1);
                f.x += __shfl_xor_sync(0xffffffffu, f.x, 2);
                f.y += __shfl_xor_sync(0xffffffffu, f.y, 2);
                sv[rp][c][0] = f.x;
                sv[rp][c][1] = f.y;
            }

        // lane picks rowpair q (rows rowA, rowA+1), all 4 gates
        float gA[4], gB[4];
#pragma unroll
        for (int c = 0; c < 4; c++) {
            gA[c] = (q == 0) ? sv[0][c][0] : (q == 1) ? sv[1][c][0]
                  : (q == 2) ? sv[2][c][0] : sv[3][c][0];
            gB[c] = (q == 0) ? sv[0][c][1] : (q == 1) ? sv[1][c][1]
                  : (q == 2) ? sv[2][c][1] : sv[3][c][1];
        }

        // ---- fused LSTM cell (2 cells per thread) ----
        {
            float it = fsig (gA[0] + xvA.x);
            float ft = fsig (gA[1] + xvA.y);
            float gt = ftanh(gA[2] + xvA.z);
            float ot = fsig (gA[3] + xvA.w);
            cA = ft * cA + it * gt;
            h_out[(size_t)(b0 + rowA) * HSZ + u0] = ot * ftanh(cA);
        }
        {
            float it = fsig (gB[0] + xvB.x);
            float ft = fsig (gB[1] + xvB.y);
            float gt = ftanh(gB[2] + xvB.z);
            float ot = fsig (gB[3] + xvB.w);
            cB = ft * cB + it * gt;
            h_out[(size_t)(b0 + rowA + 1) * HSZ + u0] = ot * ftanh(cB);
        }

        // ---- per-group grid barrier (32 blocks; wrap-safe) ----
        if (t < SEQ - 1) {
            __syncthreads();
            if (tid == 0) {
                arrive_release(bar);
                unsigned target = (unsigned)(t + 1) * 32u;
                while ((int)(poll_acquire(bar) - target) < 0) { }
            }
            __syncthreads();
        }
    }
}

// ---------------- launch ----------------------------------------------------
extern "C" void kernel_launch(void* const* d_in, const int* in_sizes, int n_in,
                              void* d_out, int out_size) {
    const float* x   = (const float*)d_in[0];
    const float* Wui = (const float*)d_in[1];
    const float* Whi = (const float*)d_in[2];
    const float* bi  = (const float*)d_in[3];
    const float* Wuf = (const float*)d_in[4];
    const float* Whf = (const float*)d_in[5];
    const float* bf  = (const float*)d_in[6];
    const float* Wug = (const float*)d_in[7];
    const float* Whg = (const float*)d_in[8];
    const float* bg  = (const float*)d_in[9];
    const float* Wuo = (const float*)d_in[10];
    const float* Who = (const float*)d_in[11];
    const float* bo  = (const float*)d_in[12];
    float* out = (float*)d_out;

    cudaFuncSetAttribute(lstm_persistent,
                         cudaFuncAttributeMaxDynamicSharedMemorySize, P_SMEM_BYTES);

    dim3 xu_grid(G4 / XBN, (SEQ * BATCH) / XBM);   // (32, 2048)
    xu_kernel<<<xu_grid, 256>>>(x, Wui, Wuf, Wug, Wuo, bi, bf, bg, bo);

    lstm_persistent<<<PBLKS, 512, P_SMEM_BYTES>>>(out, Whi, Whf, Whg, Who);
}

// round 12
// speedup vs baseline: 1.4046x; 1.4046x over previous
#include <cuda_runtime.h>
#include <cuda_bf16.h>
#include <math.h>
#include <stdint.h>

#define BATCH 256
#define SEQ   512
#define ISZ   256
#define HSZ   512
#define G4    2048   // 4*HSZ gate-interleaved: col j = u*4 + g, g in {i,f,g,o}

typedef unsigned long long ull;

// ---------------- device scratch (allocation-free) ----------------
__device__ float g_xu[(size_t)SEQ * BATCH * G4];       // xu[t][b][j] fp32
__device__ __nv_bfloat16 g_hh[BATCH * HSZ];            // h hi (bf16)
__device__ __nv_bfloat16 g_hl[BATCH * HSZ];            // h lo (bf16)
__device__ unsigned g_arr[64];                         // 2 M-group barriers @ [0],[32]

// ---------------- helpers ----------------
__device__ __forceinline__ ull fma2(ull a, ull b, ull c) {
    ull d;
    asm("fma.rn.f32x2 %0, %1, %2, %3;" : "=l"(d) : "l"(a), "l"(b), "l"(c));
    return d;
}
__device__ __forceinline__ float2 unpk(ull v) {
    float2 r;
    asm("mov.b64 {%0, %1}, %2;" : "=f"(r.x), "=f"(r.y) : "l"(v));
    return r;
}
__device__ __forceinline__ float fsig(float x)  { return 1.0f / (1.0f + __expf(-x)); }
__device__ __forceinline__ float ftanh(float x) { return 2.0f / (1.0f + __expf(-2.0f * x)) - 1.0f; }

__device__ __forceinline__ void arrive_release(unsigned* p) {
    asm volatile("red.release.gpu.global.add.u32 [%0], 1;" :: "l"(p) : "memory");
}
__device__ __forceinline__ unsigned poll_acquire(const unsigned* p) {
    unsigned v;
    asm volatile("ld.acquire.gpu.global.u32 %0, [%1];" : "=r"(v) : "l"(p) : "memory");
    return v;
}

// warp-level MMA primitives (baseline PTX, valid on compute_103)
__device__ __forceinline__ void ldmx4(uint32_t* r, uint32_t addr) {
    asm volatile("ldmatrix.sync.aligned.m8n8.x4.shared.b16 {%0,%1,%2,%3}, [%4];"
                 : "=r"(r[0]), "=r"(r[1]), "=r"(r[2]), "=r"(r[3]) : "r"(addr));
}
__device__ __forceinline__ void mma_bf16(float* c, const uint32_t* a, const uint32_t* b) {
    asm volatile(
        "mma.sync.aligned.m16n8k16.row.col.f32.bf16.bf16.f32 "
        "{%0,%1,%2,%3}, {%4,%5,%6,%7}, {%8,%9}, {%0,%1,%2,%3};"
        : "+f"(c[0]), "+f"(c[1]), "+f"(c[2]), "+f"(c[3])
        : "r"(a[0]), "r"(a[1]), "r"(a[2]), "r"(a[3]), "r"(b[0]), "r"(b[1]));
}

// ============ phase 1: xu = x @ Wu (interleaved on the fly) + bias ==========
#define XBM 64
#define XBN 64
#define XBK 16
#define XAS 34

__global__ __launch_bounds__(256) void xu_kernel(
    const float* __restrict__ x,
    const float* __restrict__ Wui, const float* __restrict__ Wuf,
    const float* __restrict__ Wug, const float* __restrict__ Wuo,
    const float* __restrict__ bi,  const float* __restrict__ bf,
    const float* __restrict__ bg,  const float* __restrict__ bo) {
    __shared__ float As[XBM * XAS];
    __shared__ float Bs[XBK * XBN];

    if (blockIdx.x == 0 && blockIdx.y == 0 && threadIdx.x < 2)
        g_arr[threadIdx.x * 32] = 0u;

    int m0 = blockIdx.y * XBM;
    int n0 = blockIdx.x * XBN;
    int tid = threadIdx.x;
    int tx = tid & 15;
    int ty = tid >> 4;

    int prow = tid >> 2;
    int pkof = (tid & 3) * 4;
    int brow = tid >> 4;
    int bu   = tid & 15;

    int m = m0 + prow;
    int t = m >> 8;
    int b = m & 255;
    const float* aptr = x + (size_t)b * (SEQ * ISZ) + (size_t)t * ISZ + pkof;
    int ubase = (n0 >> 2) + bu;

    ull acc[4][2] = {};

    for (int k0 = 0; k0 < ISZ; k0 += XBK) {
        float4 av = *(const float4*)(aptr + k0);
        *(float2*)&As[prow * XAS + 2 * (pkof + 0)] = make_float2(av.x, av.x);
        *(float2*)&As[prow * XAS + 2 * (pkof + 1)] = make_float2(av.y, av.y);
        *(float2*)&As[prow * XAS + 2 * (pkof + 2)] = make_float2(av.z, av.z);
        *(float2*)&As[prow * XAS + 2 * (pkof + 3)] = make_float2(av.w, av.w);
        int kr = (k0 + brow) * HSZ + ubase;
        Bs[brow * XBN + bu * 4 + 0] = Wui[kr];
        Bs[brow * XBN + bu * 4 + 1] = Wuf[kr];
        Bs[brow * XBN + bu * 4 + 2] = Wug[kr];
        Bs[brow * XBN + bu * 4 + 3] = Wuo[kr];
        __syncthreads();

#pragma unroll
        for (int kk = 0; kk < XBK; kk++) {
            ulonglong2 b2 = *(const ulonglong2*)&Bs[kk * XBN + tx * 4];
#pragma unroll
            for (int r = 0; r < 4; r++) {
                ull a2 = *(const ull*)&As[(ty * 4 + r) * XAS + 2 * kk];
                acc[r][0] = fma2(a2, b2.x, acc[r][0]);
                acc[r][1] = fma2(a2, b2.y, acc[r][1]);
            }
        }
        __syncthreads();
    }

    int u = (n0 >> 2) + tx;
    float4 bias = {bi[u], bf[u], bg[u], bo[u]};
#pragma unroll
    for (int r = 0; r < 4; r++) {
        float2 lo = unpk(acc[r][0]);
        float2 hi = unpk(acc[r][1]);
        float4 ov = {lo.x + bias.x, lo.y + bias.y, hi.x + bias.z, hi.y + bias.w};
        *(float4*)(g_xu + (size_t)(m0 + ty * 4 + r) * G4 + n0 + tx * 4) = ov;
    }
}

// ============ phase 2: PERSISTENT mma.sync bf16x3 recurrence =================
// 128 CTAs = 2 M-groups x 64 n-tiles; CTA tile C[128 batch][32 gate-cols].
// 8 warps (4M x 2N), warp tile 32x16, m16n8k16 bf16 MMA, fp32 accum.
// W_h slice [32 n][512 k] bf16 hi+lo resident in smem (padded, ldmatrix
// conflict-free). h staged per-64k chunk hi+lo, double-buffered.
// Smem byte layout (from 1KB-aligned base):
//   Whi @ 0      (32 x 1040B = 33280)
//   Wlo @ 33280
//   A   @ 66560  [dbuf(2)][arr(2)] x (128 rows x 144B) = 4 x 18432
//   CS  @ 140288 (128 x 144B fp32, stride 36 floats)
#define W_STRIDE_B 1040
#define A_STRIDE_B 144
#define A_OFF      66560u
#define A_BUF_B    18432u
#define CS_OFF     140288u
#define CS_STRIDE  36
#define DYN_BYTES  (158720 + 1024)

__global__ __launch_bounds__(256, 1)
void lstm_mma(float* __restrict__ out,
              const float* __restrict__ Whi, const float* __restrict__ Whf,
              const float* __restrict__ Whg, const float* __restrict__ Who) {
    extern __shared__ char s8[];
    uint32_t raw;
    asm("{ .reg .u64 t; cvta.to.shared.u64 t, %1; cvt.u32.u64 %0, t; }"
        : "=r"(raw) : "l"(s8));
    uint32_t base = (raw + 1023) & ~1023u;
    char* dynb = s8 + (base - raw);
    float* CS = (float*)(dynb + CS_OFF);

    int tid = threadIdx.x;
    int l = tid & 31;
    int warp = tid >> 5;
    int wm = warp & 3;           // M warp (32 rows)
    int wn = warp >> 2;          // N warp (16 cols)

    int nt = blockIdx.x & 63;    // n-tile (32 gate cols = 8 units)
    int mg = blockIdx.x >> 6;    // M-group
    int ncol0 = nt * 32;         // xu col base
    int u0 = nt * 8;
    int b0 = mg * 128;
    unsigned* bar = &g_arr[mg * 32];

    // ---- one-time: W_h slice -> bf16 hi/lo, padded [n][k] ----
    for (int e = tid; e < 32 * 512; e += 256) {
        int n = e >> 9, k = e & 511;
        int u = u0 + (n >> 2), g = n & 3;
        const float* W = (g == 0) ? Whi : (g == 1) ? Whf : (g == 2) ? Whg : Who;
        float w = W[k * HSZ + u];
        __nv_bfloat16 hi = __float2bfloat16(w);
        __nv_bfloat16 lo = __float2bfloat16(w - __bfloat162float(hi));
        *(__nv_bfloat16*)(dynb + n * W_STRIDE_B + k * 2) = hi;
        *(__nv_bfloat16*)(dynb + 33280 + n * W_STRIDE_B + k * 2) = lo;
    }
    __syncthreads();

    // ldmatrix lane address components
    int amrow = (l & 7) + ((l >> 3) & 1) * 8;          // 0..15
    int acolb = ((l >> 4) * 8) * 2;                     // 0 or 16 bytes
    uint32_t aoff0 = (uint32_t)(wm * 32 + amrow) * A_STRIDE_B + acolb;
    uint32_t aoff1 = aoff0 + 16u * A_STRIDE_B;
    int bnrow = wn * 16 + (l & 7) + ((l >> 4) & 1) * 8;
    int bkclb = (((l >> 3) & 1) * 8) * 2;
    uint32_t boff_hi = base + (uint32_t)bnrow * W_STRIDE_B + bkclb;
    uint32_t boff_lo = boff_hi + 33280u;

    // staging mapping: tid<128 -> hi array, >=128 -> lo; one row of 64 k each
    int srow = tid & 127;
    int sarr = tid >> 7;
    const __nv_bfloat16* hsrc = sarr ? g_hl : g_hh;
    uint32_t sdst = A_OFF + (uint32_t)sarr * A_BUF_B + (uint32_t)srow * A_STRIDE_B;

    // epilogue mapping: thread -> (row, col half)
    int erow = tid >> 1;
    int euh = tid & 1;

    float c4[4] = {0.f, 0.f, 0.f, 0.f};
    float cacc[2][2][4];

    for (int t = 0; t < SEQ; t++) {
        if (t > 0) {
#pragma unroll
            for (int mt = 0; mt < 2; mt++)
#pragma unroll
                for (int ntl = 0; ntl < 2; ntl++)
#pragma unroll
                    for (int j = 0; j < 4; j++) cacc[mt][ntl][j] = 0.f;

            const __nv_bfloat16* gsrc = hsrc + (size_t)(b0 + srow) * HSZ;
            uint4 p[8];
#pragma unroll
            for (int j = 0; j < 8; j++)
                p[j] = __ldcg((const uint4*)(gsrc + j * 8));
#pragma unroll
            for (int j = 0; j < 8; j++)
                *(uint4*)(dynb + sdst + j * 16) = p[j];
            __syncthreads();

            for (int cc = 0; cc < 8; cc++) {
                if (cc < 7) {
#pragma unroll
                    for (int j = 0; j < 8; j++)
                        p[j] = __ldcg((const uint4*)(gsrc + (cc + 1) * 64 + j * 8));
                }

                uint32_t abh = base + A_OFF + (uint32_t)(cc & 1) * (2 * A_BUF_B);
                uint32_t abl = abh + A_BUF_B;
#pragma unroll
                for (int ks = 0; ks < 4; ks++) {
                    int ksg = cc * 4 + ks;
                    uint32_t ka = (uint32_t)(ks * 32);
                    uint32_t kb = (uint32_t)(ksg * 32);
                    uint32_t ah0[4], ah1[4], al0[4], al1[4], bh[4], bl[4];
                    ldmx4(ah0, abh + aoff0 + ka);
                    ldmx4(ah1, abh + aoff1 + ka);
                    ldmx4(al0, abl + aoff0 + ka);
                    ldmx4(al1, abl + aoff1 + ka);
                    ldmx4(bh, boff_hi + kb);
                    ldmx4(bl, boff_lo + kb);
                    // hi*hi
                    mma_bf16(cacc[0][0], ah0, bh + 0);
                    mma_bf16(cacc[0][1], ah0, bh + 2);
                    mma_bf16(cacc[1][0], ah1, bh + 0);
                    mma_bf16(cacc[1][1], ah1, bh + 2);
                    // hi*lo
                    mma_bf16(cacc[0][0], ah0, bl + 0);
                    mma_bf16(cacc[0][1], ah0, bl + 2);
                    mma_bf16(cacc[1][0], ah1, bl + 0);
                    mma_bf16(cacc[1][1], ah1, bl + 2);
                    // lo*hi
                    mma_bf16(cacc[0][0], al0, bh + 0);
                    mma_bf16(cacc[0][1], al0, bh + 2);
                    mma_bf16(cacc[1][0], al1, bh + 0);
                    mma_bf16(cacc[1][1], al1, bh + 2);
                }

                if (cc < 7) {
                    uint32_t dn = sdst + (uint32_t)(((cc + 1) & 1)) * (2 * A_BUF_B);
#pragma unroll
                    for (int j = 0; j < 8; j++)
                        *(uint4*)(dynb + dn + j * 16) = p[j];
                }
                __syncthreads();
            }

            // ---- C frags -> smem ----
            int crow = wm * 32 + (l >> 2);
            int ccol = wn * 16 + 2 * (l & 3);
#pragma unroll
            for (int mt = 0; mt < 2; mt++)
#pragma unroll
                for (int ntl = 0; ntl < 2; ntl++) {
                    int r = crow + mt * 16;
                    int cl = ccol + ntl * 8;
                    *(float2*)&CS[r * CS_STRIDE + cl] =
                        make_float2(cacc[mt][ntl][0], cacc[mt][ntl][1]);
                    *(float2*)&CS[(r + 8) * CS_STRIDE + cl] =
                        make_float2(cacc[mt][ntl][2], cacc[mt][ntl][3]);
                }
            __syncthreads();
        }

        // ---- fused LSTM epilogue: 1 row-half (4 units) per thread ----
        const float* xp = g_xu + ((size_t)t * BATCH + b0 + erow) * G4 + ncol0 + euh * 16;
        const float* cp = &CS[erow * CS_STRIDE + euh * 16];
        __align__(8) __nv_bfloat16 hh4[4], hl4[4];
        __align__(16) float hf4[4];
#pragma unroll
        for (int j = 0; j < 4; j++) {
            float4 xv = *(const float4*)(xp + j * 4);
            float di = 0.f, df = 0.f, dg = 0.f, do_ = 0.f;
            if (t > 0) {
                float4 dv = *(const float4*)(cp + j * 4);
                di = dv.x; df = dv.y; dg = dv.z; do_ = dv.w;
            }
            float it = fsig(di + xv.x);
            float ft = fsig(df + xv.y);
            float gt = ftanh(dg + xv.z);
            float ot = fsig(do_ + xv.w);
            c4[j] = ft * c4[j] + it * gt;
            float h = ot * ftanh(c4[j]);
            hf4[j] = h;
            __nv_bfloat16 hb = __float2bfloat16(h);
            hh4[j] = hb;
            hl4[j] = __float2bfloat16(h - __bfloat162float(hb));
        }
        size_t ho = (size_t)(b0 + erow) * HSZ + u0 + euh * 4;
        if (t == SEQ - 1) {
            *(float4*)(out + ho) = *(float4*)hf4;
        } else {
            *(uint2*)(g_hh + ho) = *(uint2*)hh4;
            *(uint2*)(g_hl + ho) = *(uint2*)hl4;
        }

        // ---- per-M-group grid barrier (64 CTAs; wrap-safe) ----
        if (t < SEQ - 1) {
            __syncthreads();
            if (tid == 0) {
                arrive_release(bar);
                unsigned target = (unsigned)(t + 1) * 64u;
                while ((int)(poll_acquire(bar) - target) < 0) { }
            }
            __syncthreads();
        }
    }
}

// ---------------- launch ----------------------------------------------------
extern "C" void kernel_launch(void* const* d_in, const int* in_sizes, int n_in,
                              void* d_out, int out_size) {
    const float* x   = (const float*)d_in[0];
    const float* Wui = (const float*)d_in[1];
    const float* Whi = (const float*)d_in[2];
    const float* bi  = (const float*)d_in[3];
    const float* Wuf = (const float*)d_in[4];
    const float* Whf = (const float*)d_in[5];
    const float* bf  = (const float*)d_in[6];
    const float* Wug = (const float*)d_in[7];
    const float* Whg = (const float*)d_in[8];
    const float* bg  = (const float*)d_in[9];
    const float* Wuo = (const float*)d_in[10];
    const float* Who = (const float*)d_in[11];
    const float* bo  = (const float*)d_in[12];
    float* out = (float*)d_out;

    cudaFuncSetAttribute(lstm_mma,
                         cudaFuncAttributeMaxDynamicSharedMemorySize, DYN_BYTES);

    dim3 xu_grid(G4 / XBN, (SEQ * BATCH) / XBM);   // (32, 2048)
    xu_kernel<<<xu_grid, 256>>>(x, Wui, Wuf, Wug, Wuo, bi, bf, bg, bo);

    lstm_mma<<<128, 256, DYN_BYTES>>>(out, Whi, Whf, Whg, Who);
}

// round 13
// speedup vs baseline: 1.4159x; 1.0080x over previous
#include <cuda_runtime.h>
#include <cuda_bf16.h>
#include <math.h>
#include <stdint.h>

#define BATCH 256
#define SEQ   512
#define ISZ   256
#define HSZ   512
#define G4    2048   // 4*HSZ gate-interleaved: col j = u*4 + g, g in {i,f,g,o}

typedef unsigned long long ull;

// ---------------- device scratch (allocation-free) ----------------
__device__ float g_xu[(size_t)SEQ * BATCH * G4];       // xu[t][b][j] fp32
__device__ __nv_bfloat16 g_hh[BATCH * HSZ];            // h hi (bf16)
__device__ __nv_bfloat16 g_hl[BATCH * HSZ];            // h lo (bf16)
__device__ unsigned g_arr[64];                         // 2 M-group barriers @ [0],[32]

// ---------------- helpers ----------------
__device__ __forceinline__ ull fma2(ull a, ull b, ull c) {
    ull d;
    asm("fma.rn.f32x2 %0, %1, %2, %3;" : "=l"(d) : "l"(a), "l"(b), "l"(c));
    return d;
}
__device__ __forceinline__ float2 unpk(ull v) {
    float2 r;
    asm("mov.b64 {%0, %1}, %2;" : "=f"(r.x), "=f"(r.y) : "l"(v));
    return r;
}
__device__ __forceinline__ float fsig(float x)  { return 1.0f / (1.0f + __expf(-x)); }
__device__ __forceinline__ float ftanh(float x) { return 2.0f / (1.0f + __expf(-2.0f * x)) - 1.0f; }

__device__ __forceinline__ void arrive_release(unsigned* p) {
    asm volatile("red.release.gpu.global.add.u32 [%0], 1;" :: "l"(p) : "memory");
}
__device__ __forceinline__ unsigned poll_acquire(const unsigned* p) {
    unsigned v;
    asm volatile("ld.acquire.gpu.global.u32 %0, [%1];" : "=r"(v) : "l"(p) : "memory");
    return v;
}

// warp-level MMA primitives (baseline PTX, valid on compute_103)
__device__ __forceinline__ void ldmx4(uint32_t* r, uint32_t addr) {
    asm volatile("ldmatrix.sync.aligned.m8n8.x4.shared.b16 {%0,%1,%2,%3}, [%4];"
                 : "=r"(r[0]), "=r"(r[1]), "=r"(r[2]), "=r"(r[3]) : "r"(addr));
}
__device__ __forceinline__ void mma_bf16(float* c, const uint32_t* a, const uint32_t* b) {
    asm volatile(
        "mma.sync.aligned.m16n8k16.row.col.f32.bf16.bf16.f32 "
        "{%0,%1,%2,%3}, {%4,%5,%6,%7}, {%8,%9}, {%0,%1,%2,%3};"
        : "+f"(c[0]), "+f"(c[1]), "+f"(c[2]), "+f"(c[3])
        : "r"(a[0]), "r"(a[1]), "r"(a[2]), "r"(a[3]), "r"(b[0]), "r"(b[1]));
}

// ============ phase 1: xu = x @ Wu (interleaved on the fly) + bias ==========
#define XBM 64
#define XBN 64
#define XBK 16
#define XAS 34

__global__ __launch_bounds__(256) void xu_kernel(
    const float* __restrict__ x,
    const float* __restrict__ Wui, const float* __restrict__ Wuf,
    const float* __restrict__ Wug, const float* __restrict__ Wuo,
    const float* __restrict__ bi,  const float* __restrict__ bf,
    const float* __restrict__ bg,  const float* __restrict__ bo) {
    __shared__ float As[XBM * XAS];
    __shared__ float Bs[XBK * XBN];

    if (blockIdx.x == 0 && blockIdx.y == 0 && threadIdx.x < 2)
        g_arr[threadIdx.x * 32] = 0u;

    int m0 = blockIdx.y * XBM;
    int n0 = blockIdx.x * XBN;
    int tid = threadIdx.x;
    int tx = tid & 15;
    int ty = tid >> 4;

    int prow = tid >> 2;
    int pkof = (tid & 3) * 4;
    int brow = tid >> 4;
    int bu   = tid & 15;

    int m = m0 + prow;
    int t = m >> 8;
    int b = m & 255;
    const float* aptr = x + (size_t)b * (SEQ * ISZ) + (size_t)t * ISZ + pkof;
    int ubase = (n0 >> 2) + bu;

    ull acc[4][2] = {};

    for (int k0 = 0; k0 < ISZ; k0 += XBK) {
        float4 av = *(const float4*)(aptr + k0);
        *(float2*)&As[prow * XAS + 2 * (pkof + 0)] = make_float2(av.x, av.x);
        *(float2*)&As[prow * XAS + 2 * (pkof + 1)] = make_float2(av.y, av.y);
        *(float2*)&As[prow * XAS + 2 * (pkof + 2)] = make_float2(av.z, av.z);
        *(float2*)&As[prow * XAS + 2 * (pkof + 3)] = make_float2(av.w, av.w);
        int kr = (k0 + brow) * HSZ + ubase;
        Bs[brow * XBN + bu * 4 + 0] = Wui[kr];
        Bs[brow * XBN + bu * 4 + 1] = Wuf[kr];
        Bs[brow * XBN + bu * 4 + 2] = Wug[kr];
        Bs[brow * XBN + bu * 4 + 3] = Wuo[kr];
        __syncthreads();

#pragma unroll
        for (int kk = 0; kk < XBK; kk++) {
            ulonglong2 b2 = *(const ulonglong2*)&Bs[kk * XBN + tx * 4];
#pragma unroll
            for (int r = 0; r < 4; r++) {
                ull a2 = *(const ull*)&As[(ty * 4 + r) * XAS + 2 * kk];
                acc[r][0] = fma2(a2, b2.x, acc[r][0]);
                acc[r][1] = fma2(a2, b2.y, acc[r][1]);
            }
        }
        __syncthreads();
    }

    int u = (n0 >> 2) + tx;
    float4 bias = {bi[u], bf[u], bg[u], bo[u]};
#pragma unroll
    for (int r = 0; r < 4; r++) {
        float2 lo = unpk(acc[r][0]);
        float2 hi = unpk(acc[r][1]);
        float4 ov = {lo.x + bias.x, lo.y + bias.y, hi.x + bias.z, hi.y + bias.w};
        *(float4*)(g_xu + (size_t)(m0 + ty * 4 + r) * G4 + n0 + tx * 4) = ov;
    }
}

// ============ phase 2: PERSISTENT mma.sync, WARP-SPECIALIZED =================
// 128 CTAs = 2 M-groups x 64 n-tiles; CTA tile C[128 batch][32 gate-cols].
// 512 threads: warps 0-7 = MMA consumers (4M x 2N, warp tile 32x16, m16n8k16
// bf16, fp32 accum, bf16 hi/lo x3 split); warps 8-15 = producers staging h
// chunks (64 k, double-buffered). W_h slice resident in smem.
// Smem byte layout (from 1KB-aligned base):
//   Whi @ 0      (32 x 1040B = 33280)
//   Wlo @ 33280
//   A   @ 66560  [dbuf(2)][arr(2)] x (128 rows x 144B) = 4 x 18432
//   CS  @ 140288 (128 x 144B fp32, stride 36 floats)
#define W_STRIDE_B 1040
#define A_STRIDE_B 144
#define A_OFF      66560u
#define A_BUF_B    18432u
#define CS_OFF     140288u
#define CS_STRIDE  36
#define DYN_BYTES  (158720 + 1024)

__global__ __launch_bounds__(512, 1)
void lstm_mma(float* __restrict__ out,
              const float* __restrict__ Whi, const float* __restrict__ Whf,
              const float* __restrict__ Whg, const float* __restrict__ Who) {
    extern __shared__ char s8[];
    uint32_t raw;
    asm("{ .reg .u64 t; cvta.to.shared.u64 t, %1; cvt.u32.u64 %0, t; }"
        : "=r"(raw) : "l"(s8));
    uint32_t base = (raw + 1023) & ~1023u;
    char* dynb = s8 + (base - raw);
    float* CS = (float*)(dynb + CS_OFF);

    int tid = threadIdx.x;
    int l = tid & 31;
    int warp = tid >> 5;
    int is_mma = (warp < 8);
    int wm = warp & 3;           // M warp (32 rows)     [mma warps]
    int wn = (warp >> 2) & 1;    // N warp (16 cols)

    int nt = blockIdx.x & 63;    // n-tile (32 gate cols = 8 units)
    int mg = blockIdx.x >> 6;    // M-group
    int ncol0 = nt * 32;         // xu col base
    int u0 = nt * 8;
    int b0 = mg * 128;
    unsigned* bar = &g_arr[mg * 32];

    // ---- one-time: W_h slice -> bf16 hi/lo, padded [n][k] ----
    for (int e = tid; e < 32 * 512; e += 512) {
        int n = e >> 9, k = e & 511;
        int u = u0 + (n >> 2), g = n & 3;
        const float* W = (g == 0) ? Whi : (g == 1) ? Whf : (g == 2) ? Whg : Who;
        float w = W[k * HSZ + u];
        __nv_bfloat16 hi = __float2bfloat16(w);
        __nv_bfloat16 lo = __float2bfloat16(w - __bfloat162float(hi));
        *(__nv_bfloat16*)(dynb + n * W_STRIDE_B + k * 2) = hi;
        *(__nv_bfloat16*)(dynb + 33280 + n * W_STRIDE_B + k * 2) = lo;
    }
    __syncthreads();

    // ldmatrix lane address components (mma warps)
    int amrow = (l & 7) + ((l >> 3) & 1) * 8;          // 0..15
    int acolb = ((l >> 4) * 8) * 2;                     // 0 or 16 bytes
    uint32_t aoff0 = (uint32_t)(wm * 32 + amrow) * A_STRIDE_B + acolb;
    uint32_t aoff1 = aoff0 + 16u * A_STRIDE_B;
    int bnrow = wn * 16 + (l & 7) + ((l >> 4) & 1) * 8;
    int bkclb = (((l >> 3) & 1) * 8) * 2;
    uint32_t boff_hi = base + (uint32_t)bnrow * W_STRIDE_B + bkclb;
    uint32_t boff_lo = boff_hi + 33280u;

    // producer staging mapping (warps 8-15): ptid 0..255
    int ptid = tid - 256;
    int srow = ptid & 127;
    int sarr = (ptid >> 7) & 1;
    const __nv_bfloat16* hsrc = sarr ? g_hl : g_hh;
    uint32_t sdst = A_OFF + (uint32_t)sarr * A_BUF_B + (uint32_t)srow * A_STRIDE_B;

    // epilogue mapping: 512 threads, 2 cells each (1 row x 2 units)
    int erow = tid >> 2;         // 0..127
    int eq   = tid & 3;          // unit pair (8 cols)

    float c2[2] = {0.f, 0.f};
    float cacc[2][2][4];

    for (int t = 0; t < SEQ; t++) {
        if (t > 0) {
            if (is_mma) {
#pragma unroll
                for (int mt = 0; mt < 2; mt++)
#pragma unroll
                    for (int ntl = 0; ntl < 2; ntl++)
#pragma unroll
                        for (int j = 0; j < 4; j++) cacc[mt][ntl][j] = 0.f;
            } else {
                // producers: fill chunk 0 into buf 0
                const __nv_bfloat16* gsrc = hsrc + (size_t)(b0 + srow) * HSZ;
                uint4 p[8];
#pragma unroll
                for (int j = 0; j < 8; j++)
                    p[j] = __ldcg((const uint4*)(gsrc + j * 8));
#pragma unroll
                for (int j = 0; j < 8; j++)
                    *(uint4*)(dynb + sdst + j * 16) = p[j];
            }
            __syncthreads();

            for (int cc = 0; cc < 8; cc++) {
                if (is_mma) {
                    uint32_t abh = base + A_OFF + (uint32_t)(cc & 1) * (2 * A_BUF_B);
                    uint32_t abl = abh + A_BUF_B;
#pragma unroll
                    for (int ks = 0; ks < 4; ks++) {
                        int ksg = cc * 4 + ks;
                        uint32_t ka = (uint32_t)(ks * 32);
                        uint32_t kb = (uint32_t)(ksg * 32);
                        uint32_t ah0[4], ah1[4], al0[4], al1[4], bh[4], bl[4];
                        ldmx4(ah0, abh + aoff0 + ka);
                        ldmx4(ah1, abh + aoff1 + ka);
                        ldmx4(al0, abl + aoff0 + ka);
                        ldmx4(al1, abl + aoff1 + ka);
                        ldmx4(bh, boff_hi + kb);
                        ldmx4(bl, boff_lo + kb);
                        // hi*hi
                        mma_bf16(cacc[0][0], ah0, bh + 0);
                        mma_bf16(cacc[0][1], ah0, bh + 2);
                        mma_bf16(cacc[1][0], ah1, bh + 0);
                        mma_bf16(cacc[1][1], ah1, bh + 2);
                        // hi*lo
                        mma_bf16(cacc[0][0], ah0, bl + 0);
                        mma_bf16(cacc[0][1], ah0, bl + 2);
                        mma_bf16(cacc[1][0], ah1, bl + 0);
                        mma_bf16(cacc[1][1], ah1, bl + 2);
                        // lo*hi
                        mma_bf16(cacc[0][0], al0, bh + 0);
                        mma_bf16(cacc[0][1], al0, bh + 2);
                        mma_bf16(cacc[1][0], al1, bh + 0);
                        mma_bf16(cacc[1][1], al1, bh + 2);
                    }
                } else if (cc < 7) {
                    // producers: fill chunk cc+1 into buf (cc+1)&1
                    const __nv_bfloat16* gsrc = hsrc + (size_t)(b0 + srow) * HSZ
                                              + (cc + 1) * 64;
                    uint4 p[8];
#pragma unroll
                    for (int j = 0; j < 8; j++)
                        p[j] = __ldcg((const uint4*)(gsrc + j * 8));
                    uint32_t dn = sdst + (uint32_t)((cc + 1) & 1) * (2 * A_BUF_B);
#pragma unroll
                    for (int j = 0; j < 8; j++)
                        *(uint4*)(dynb + dn + j * 16) = p[j];
                }
                __syncthreads();
            }

            // ---- C frags -> smem (mma warps only) ----
            if (is_mma) {
                int crow = wm * 32 + (l >> 2);
                int ccol = wn * 16 + 2 * (l & 3);
#pragma unroll
                for (int mt = 0; mt < 2; mt++)
#pragma unroll
                    for (int ntl = 0; ntl < 2; ntl++) {
                        int r = crow + mt * 16;
                        int cl = ccol + ntl * 8;
                        *(float2*)&CS[r * CS_STRIDE + cl] =
                            make_float2(cacc[mt][ntl][0], cacc[mt][ntl][1]);
                        *(float2*)&CS[(r + 8) * CS_STRIDE + cl] =
                            make_float2(cacc[mt][ntl][2], cacc[mt][ntl][3]);
                    }
            }
            __syncthreads();
        }

        // ---- fused LSTM epilogue: 512 threads, 1 row x 2 units each ----
        const float* xp = g_xu + ((size_t)t * BATCH + b0 + erow) * G4 + ncol0 + eq * 8;
        const float* cp = &CS[erow * CS_STRIDE + eq * 8];
        __align__(4) __nv_bfloat16 hh2[2], hl2[2];
        float hf2[2];
#pragma unroll
        for (int j = 0; j < 2; j++) {
            float4 xv = *(const float4*)(xp + j * 4);
            float di = 0.f, df = 0.f, dg = 0.f, do_ = 0.f;
            if (t > 0) {
                float4 dv = *(const float4*)(cp + j * 4);
                di = dv.x; df = dv.y; dg = dv.z; do_ = dv.w;
            }
            float it = fsig(di + xv.x);
            float ft = fsig(df + xv.y);
            float gt = ftanh(dg + xv.z);
            float ot = fsig(do_ + xv.w);
            c2[j] = ft * c2[j] + it * gt;
            float h = ot * ftanh(c2[j]);
            hf2[j] = h;
            __nv_bfloat16 hb = __float2bfloat16(h);
            hh2[j] = hb;
            hl2[j] = __float2bfloat16(h - __bfloat162float(hb));
        }
        size_t ho = (size_t)(b0 + erow) * HSZ + u0 + eq * 2;
        if (t == SEQ - 1) {
            *(float2*)(out + ho) = make_float2(hf2[0], hf2[1]);
        } else {
            *(uint32_t*)(g_hh + ho) = *(uint32_t*)hh2;
            *(uint32_t*)(g_hl + ho) = *(uint32_t*)hl2;
        }

        // ---- per-M-group grid barrier (64 CTAs; wrap-safe) ----
        if (t < SEQ - 1) {
            __syncthreads();
            if (tid == 0) {
                arrive_release(bar);
                unsigned target = (unsigned)(t + 1) * 64u;
                while ((int)(poll_acquire(bar) - target) < 0) { }
            }
            __syncthreads();
        }
    }
}

// ---------------- launch ----------------------------------------------------
extern "C" void kernel_launch(void* const* d_in, const int* in_sizes, int n_in,
                              void* d_out, int out_size) {
    const float* x   = (const float*)d_in[0];
    const float* Wui = (const float*)d_in[1];
    const float* Whi = (const float*)d_in[2];
    const float* bi  = (const float*)d_in[3];
    const float* Wuf = (const float*)d_in[4];
    const float* Whf = (const float*)d_in[5];
    const float* bf  = (const float*)d_in[6];
    const float* Wug = (const float*)d_in[7];
    const float* Whg = (const float*)d_in[8];
    const float* bg  = (const float*)d_in[9];
    const float* Wuo = (const float*)d_in[10];
    const float* Who = (const float*)d_in[11];
    const float* bo  = (const float*)d_in[12];
    float* out = (float*)d_out;

    cudaFuncSetAttribute(lstm_mma,
                         cudaFuncAttributeMaxDynamicSharedMemorySize, DYN_BYTES);

    dim3 xu_grid(G4 / XBN, (SEQ * BATCH) / XBM);   // (32, 2048)
    xu_kernel<<<xu_grid, 256>>>(x, Wui, Wuf, Wug, Wuo, bi, bf, bg, bo);

    lstm_mma<<<128, 512, DYN_BYTES>>>(out, Whi, Whf, Whg, Who);
}

// round 14
// speedup vs baseline: 1.9932x; 1.4077x over previous
#include <cuda_runtime.h>
#include <cuda_bf16.h>
#include <math.h>
#include <stdint.h>

#define BATCH 256
#define SEQ   512
#define ISZ   256
#define HSZ   512
#define G4    2048   // 4*HSZ gate-interleaved: col j = u*4 + g, g in {i,f,g,o}

typedef unsigned long long ull;

// ---------------- device scratch (allocation-free) ----------------
__device__ float g_xu[(size_t)SEQ * BATCH * G4];       // xu[t][b][j] fp32
__device__ __nv_bfloat16 g_hh[BATCH * HSZ];            // h hi (bf16)
__device__ __nv_bfloat16 g_hl[BATCH * HSZ];            // h lo (bf16)
__device__ unsigned g_arr[64];                         // 4 M-group barriers @ 16-word spacing

// ---------------- helpers ----------------
__device__ __forceinline__ ull fma2(ull a, ull b, ull c) {
    ull d;
    asm("fma.rn.f32x2 %0, %1, %2, %3;" : "=l"(d) : "l"(a), "l"(b), "l"(c));
    return d;
}
__device__ __forceinline__ float2 unpk(ull v) {
    float2 r;
    asm("mov.b64 {%0, %1}, %2;" : "=f"(r.x), "=f"(r.y) : "l"(v));
    return r;
}
__device__ __forceinline__ float fsig(float x)  { return 1.0f / (1.0f + __expf(-x)); }
__device__ __forceinline__ float ftanh(float x) { return 2.0f / (1.0f + __expf(-2.0f * x)) - 1.0f; }

__device__ __forceinline__ void arrive_release(unsigned* p) {
    asm volatile("red.release.gpu.global.add.u32 [%0], 1;" :: "l"(p) : "memory");
}
__device__ __forceinline__ unsigned poll_acquire(const unsigned* p) {
    unsigned v;
    asm volatile("ld.acquire.gpu.global.u32 %0, [%1];" : "=r"(v) : "l"(p) : "memory");
    return v;
}

// warp-level MMA primitives (baseline PTX, valid on compute_103)
__device__ __forceinline__ void ldmx4(uint32_t* r, uint32_t addr) {
    asm volatile("ldmatrix.sync.aligned.m8n8.x4.shared.b16 {%0,%1,%2,%3}, [%4];"
                 : "=r"(r[0]), "=r"(r[1]), "=r"(r[2]), "=r"(r[3]) : "r"(addr));
}
__device__ __forceinline__ void mma_bf16(float* c, const uint32_t* a, const uint32_t* b) {
    asm volatile(
        "mma.sync.aligned.m16n8k16.row.col.f32.bf16.bf16.f32 "
        "{%0,%1,%2,%3}, {%4,%5,%6,%7}, {%8,%9}, {%0,%1,%2,%3};"
        : "+f"(c[0]), "+f"(c[1]), "+f"(c[2]), "+f"(c[3])
        : "r"(a[0]), "r"(a[1]), "r"(a[2]), "r"(a[3]), "r"(b[0]), "r"(b[1]));
}
__device__ __forceinline__ void cpa16(uint32_t dst, const void* src) {
    asm volatile("cp.async.cg.shared.global [%0], [%1], 16;" :: "r"(dst), "l"(src));
}
__device__ __forceinline__ void cpa_commit_wait() {
    asm volatile("cp.async.commit_group;");
    asm volatile("cp.async.wait_group 0;" ::: "memory");
}

// ============ phase 1: xu = x @ Wu (interleaved on the fly) + bias ==========
#define XBM 64
#define XBN 64
#define XBK 16
#define XAS 34

__global__ __launch_bounds__(256) void xu_kernel(
    const float* __restrict__ x,
    const float* __restrict__ Wui, const float* __restrict__ Wuf,
    const float* __restrict__ Wug, const float* __restrict__ Wuo,
    const float* __restrict__ bi,  const float* __restrict__ bf,
    const float* __restrict__ bg,  const float* __restrict__ bo) {
    __shared__ float As[XBM * XAS];
    __shared__ float Bs[XBK * XBN];

    if (blockIdx.x == 0 && blockIdx.y == 0 && threadIdx.x < 4)
        g_arr[threadIdx.x * 16] = 0u;

    int m0 = blockIdx.y * XBM;
    int n0 = blockIdx.x * XBN;
    int tid = threadIdx.x;
    int tx = tid & 15;
    int ty = tid >> 4;

    int prow = tid >> 2;
    int pkof = (tid & 3) * 4;
    int brow = tid >> 4;
    int bu   = tid & 15;

    int m = m0 + prow;
    int t = m >> 8;
    int b = m & 255;
    const float* aptr = x + (size_t)b * (SEQ * ISZ) + (size_t)t * ISZ + pkof;
    int ubase = (n0 >> 2) + bu;

    ull acc[4][2] = {};

    for (int k0 = 0; k0 < ISZ; k0 += XBK) {
        float4 av = *(const float4*)(aptr + k0);
        *(float2*)&As[prow * XAS + 2 * (pkof + 0)] = make_float2(av.x, av.x);
        *(float2*)&As[prow * XAS + 2 * (pkof + 1)] = make_float2(av.y, av.y);
        *(float2*)&As[prow * XAS + 2 * (pkof + 2)] = make_float2(av.z, av.z);
        *(float2*)&As[prow * XAS + 2 * (pkof + 3)] = make_float2(av.w, av.w);
        int kr = (k0 + brow) * HSZ + ubase;
        Bs[brow * XBN + bu * 4 + 0] = Wui[kr];
        Bs[brow * XBN + bu * 4 + 1] = Wuf[kr];
        Bs[brow * XBN + bu * 4 + 2] = Wug[kr];
        Bs[brow * XBN + bu * 4 + 3] = Wuo[kr];
        __syncthreads();

#pragma unroll
        for (int kk = 0; kk < XBK; kk++) {
            ulonglong2 b2 = *(const ulonglong2*)&Bs[kk * XBN + tx * 4];
#pragma unroll
            for (int r = 0; r < 4; r++) {
                ull a2 = *(const ull*)&As[(ty * 4 + r) * XAS + 2 * kk];
                acc[r][0] = fma2(a2, b2.x, acc[r][0]);
                acc[r][1] = fma2(a2, b2.y, acc[r][1]);
            }
        }
        __syncthreads();
    }

    int u = (n0 >> 2) + tx;
    float4 bias = {bi[u], bf[u], bg[u], bo[u]};
#pragma unroll
    for (int r = 0; r < 4; r++) {
        float2 lo = unpk(acc[r][0]);
        float2 hi = unpk(acc[r][1]);
        float4 ov = {lo.x + bias.x, lo.y + bias.y, hi.x + bias.z, hi.y + bias.w};
        *(float4*)(g_xu + (size_t)(m0 + ty * 4 + r) * G4 + n0 + tx * 4) = ov;
    }
}

// ============ phase 2: PERSISTENT mma.sync, 64x64 tiles ======================
// 128 CTAs = 4 M-groups x 32 n-tiles; CTA tile C[64 batch][64 gate-cols].
// 512 threads: warps 0-7 = MMA (2M x 4N, warp tile 32x16, m16n8k16 bf16,
// fp32 accum, bf16 hi/lo x3 split); warps 8-15 = cp.async producers staging
// h in 128-k chunks (4 chunks, double-buffered). W_h slice resident in smem.
// Smem byte layout (from 1KB-aligned base):
//   Whi @ 0      (64 x 1040B = 66560)
//   Wlo @ 66560
//   A   @ 133120 [dbuf(2)] x [arr(2) x (64 rows x 272B)] = 2 x 34816
//   CS  @ 202752 (64 rows x 272B fp32, stride 68 floats)
#define W_STRIDE_B 1040
#define A_STRIDE_B 272
#define A_OFF      133120u
#define A_ARR_B    17408u
#define A_BUF_B    34816u
#define CS_OFF     202752u
#define CS_STRIDE  68
#define DYN_BYTES  (220160 + 1024)

__global__ __launch_bounds__(512, 1)
void lstm_mma(float* __restrict__ out,
              const float* __restrict__ Whi, const float* __restrict__ Whf,
              const float* __restrict__ Whg, const float* __restrict__ Who) {
    extern __shared__ char s8[];
    uint32_t raw;
    asm("{ .reg .u64 t; cvta.to.shared.u64 t, %1; cvt.u32.u64 %0, t; }"
        : "=r"(raw) : "l"(s8));
    uint32_t base = (raw + 1023) & ~1023u;
    char* dynb = s8 + (base - raw);
    float* CS = (float*)(dynb + CS_OFF);

    int tid = threadIdx.x;
    int l = tid & 31;
    int warp = tid >> 5;
    int is_mma = (warp < 8);
    int wm = warp & 1;           // M warp (32 rows)  [mma warps]
    int wn = (warp >> 1) & 3;    // N warp (16 cols)

    int nt = blockIdx.x & 31;    // n-tile (64 gate cols = 16 units)
    int mg = blockIdx.x >> 5;    // M-group 0..3
    int ncol0 = nt * 64;         // xu col base
    int u0 = nt * 16;
    int b0 = mg * 64;
    unsigned* bar = &g_arr[mg * 16];

    // ---- one-time: W_h slice -> bf16 hi/lo, padded [n][k] ----
    for (int e = tid; e < 64 * 512; e += 512) {
        int n = e >> 9, k = e & 511;
        int u = u0 + (n >> 2), g = n & 3;
        const float* W = (g == 0) ? Whi : (g == 1) ? Whf : (g == 2) ? Whg : Who;
        float w = W[k * HSZ + u];
        __nv_bfloat16 hi = __float2bfloat16(w);
        __nv_bfloat16 lo = __float2bfloat16(w - __bfloat162float(hi));
        *(__nv_bfloat16*)(dynb + n * W_STRIDE_B + k * 2) = hi;
        *(__nv_bfloat16*)(dynb + 66560 + n * W_STRIDE_B + k * 2) = lo;
    }
    __syncthreads();

    // ldmatrix lane address components (mma warps)
    int amrow = (l & 7) + ((l >> 3) & 1) * 8;          // 0..15
    int acolb = ((l >> 4) * 8) * 2;                     // 0 or 16 bytes
    uint32_t aoff0 = (uint32_t)(wm * 32 + amrow) * A_STRIDE_B + acolb;
    uint32_t aoff1 = aoff0 + 16u * A_STRIDE_B;
    int bnrow = wn * 16 + (l & 7) + ((l >> 4) & 1) * 8;
    int bkclb = (((l >> 3) & 1) * 8) * 2;
    uint32_t boff_hi = base + (uint32_t)bnrow * W_STRIDE_B + bkclb;
    uint32_t boff_lo = boff_hi + 66560u;

    // producer staging (warps 8-15): ptid 0..255 -> (row 0..63, arr, half)
    int ptid = tid - 256;
    int srow = ptid & 63;
    int sarr = (ptid >> 6) & 1;
    int shalf = (ptid >> 7) & 1;         // which 128B (64-elem) half of the 256B chunk-row
    const __nv_bfloat16* hsrc = sarr ? g_hl : g_hh;
    uint32_t sdst = base + A_OFF + (uint32_t)sarr * A_ARR_B
                  + (uint32_t)srow * A_STRIDE_B + (uint32_t)shalf * 128u;

    // epilogue mapping: 512 threads, 1 row x 2 units (8 gates) each
    int erow = tid >> 3;         // 0..63
    int eq   = tid & 7;          // col-oct

    float c2[2] = {0.f, 0.f};
    float cacc[2][2][4];

    for (int t = 0; t < SEQ; t++) {
        // prefetch this thread's xu gates at step top (overlaps whole GEMM)
        const float* xp = g_xu + ((size_t)t * BATCH + b0 + erow) * G4 + ncol0 + eq * 8;
        float4 xv0 = __ldcg((const float4*)xp);
        float4 xv1 = __ldcg((const float4*)(xp + 4));

        if (t > 0) {
            if (is_mma) {
#pragma unroll
                for (int mt = 0; mt < 2; mt++)
#pragma unroll
                    for (int ntl = 0; ntl < 2; ntl++)
#pragma unroll
                        for (int j = 0; j < 4; j++) cacc[mt][ntl][j] = 0.f;
            } else {
                // producers: chunk 0 -> buf 0 via cp.async
                const __nv_bfloat16* gsrc = hsrc + (size_t)(b0 + srow) * HSZ + shalf * 64;
#pragma unroll
                for (int j = 0; j < 8; j++)
                    cpa16(sdst + j * 16, gsrc + j * 8);
                cpa_commit_wait();
            }
            __syncthreads();

            for (int cc = 0; cc < 4; cc++) {
                if (is_mma) {
                    uint32_t abh = base + A_OFF + (uint32_t)(cc & 1) * A_BUF_B;
                    uint32_t abl = abh + A_ARR_B;
#pragma unroll
                    for (int ks = 0; ks < 8; ks++) {
                        uint32_t ka = (uint32_t)(ks * 32);
                        uint32_t kb = (uint32_t)(cc * 256 + ks * 32);
                        uint32_t ah0[4], ah1[4], al0[4], al1[4], bh[4], bl[4];
                        ldmx4(ah0, abh + aoff0 + ka);
                        ldmx4(ah1, abh + aoff1 + ka);
                        ldmx4(al0, abl + aoff0 + ka);
                        ldmx4(al1, abl + aoff1 + ka);
                        ldmx4(bh, boff_hi + kb);
                        ldmx4(bl, boff_lo + kb);
                        // hi*hi
                        mma_bf16(cacc[0][0], ah0, bh + 0);
                        mma_bf16(cacc[0][1], ah0, bh + 2);
                        mma_bf16(cacc[1][0], ah1, bh + 0);
                        mma_bf16(cacc[1][1], ah1, bh + 2);
                        // hi*lo
                        mma_bf16(cacc[0][0], ah0, bl + 0);
                        mma_bf16(cacc[0][1], ah0, bl + 2);
                        mma_bf16(cacc[1][0], ah1, bl + 0);
                        mma_bf16(cacc[1][1], ah1, bl + 2);
                        // lo*hi
                        mma_bf16(cacc[0][0], al0, bh + 0);
                        mma_bf16(cacc[0][1], al0, bh + 2);
                        mma_bf16(cacc[1][0], al1, bh + 0);
                        mma_bf16(cacc[1][1], al1, bh + 2);
                    }
                } else if (cc < 3) {
                    // producers: chunk cc+1 -> buf (cc+1)&1
                    const __nv_bfloat16* gsrc = hsrc + (size_t)(b0 + srow) * HSZ
                                              + (cc + 1) * 128 + shalf * 64;
                    uint32_t dn = sdst + (uint32_t)((cc + 1) & 1) * A_BUF_B;
#pragma unroll
                    for (int j = 0; j < 8; j++)
                        cpa16(dn + j * 16, gsrc + j * 8);
                    cpa_commit_wait();
                }
                __syncthreads();
            }

            // ---- C frags -> smem (mma warps only) ----
            if (is_mma) {
                int crow = wm * 32 + (l >> 2);
                int ccol = wn * 16 + 2 * (l & 3);
#pragma unroll
                for (int mt = 0; mt < 2; mt++)
#pragma unroll
                    for (int ntl = 0; ntl < 2; ntl++) {
                        int r = crow + mt * 16;
                        int cl = ccol + ntl * 8;
                        *(float2*)&CS[r * CS_STRIDE + cl] =
                            make_float2(cacc[mt][ntl][0], cacc[mt][ntl][1]);
                        *(float2*)&CS[(r + 8) * CS_STRIDE + cl] =
                            make_float2(cacc[mt][ntl][2], cacc[mt][ntl][3]);
                    }
            }
            __syncthreads();
        }

        // ---- fused LSTM epilogue: 512 threads, 1 row x 2 units each ----
        const float* cp = &CS[erow * CS_STRIDE + eq * 8];
        __align__(4) __nv_bfloat16 hh2[2], hl2[2];
        float hf2[2];
#pragma unroll
        for (int j = 0; j < 2; j++) {
            float4 xv = (j == 0) ? xv0 : xv1;
            float di = 0.f, df = 0.f, dg = 0.f, do_ = 0.f;
            if (t > 0) {
                float4 dv = *(const float4*)(cp + j * 4);
                di = dv.x; df = dv.y; dg = dv.z; do_ = dv.w;
            }
            float it = fsig(di + xv.x);
            float ft = fsig(df + xv.y);
            float gt = ftanh(dg + xv.z);
            float ot = fsig(do_ + xv.w);
            c2[j] = ft * c2[j] + it * gt;
            float h = ot * ftanh(c2[j]);
            hf2[j] = h;
            __nv_bfloat16 hb = __float2bfloat16(h);
            hh2[j] = hb;
            hl2[j] = __float2bfloat16(h - __bfloat162float(hb));
        }
        size_t ho = (size_t)(b0 + erow) * HSZ + u0 + eq * 2;
        if (t == SEQ - 1) {
            *(float2*)(out + ho) = make_float2(hf2[0], hf2[1]);
        } else {
            *(uint32_t*)(g_hh + ho) = *(uint32_t*)hh2;
            *(uint32_t*)(g_hl + ho) = *(uint32_t*)hl2;
        }

        // ---- per-M-group grid barrier (32 CTAs; wrap-safe) ----
        if (t < SEQ - 1) {
            __syncthreads();
            if (tid == 0) {
                arrive_release(bar);
                unsigned target = (unsigned)(t + 1) * 32u;
                while ((int)(poll_acquire(bar) - target) < 0) { }
            }
            __syncthreads();
        }
    }
}

// ---------------- launch ----------------------------------------------------
extern "C" void kernel_launch(void* const* d_in, const int* in_sizes, int n_in,
                              void* d_out, int out_size) {
    const float* x   = (const float*)d_in[0];
    const float* Wui = (const float*)d_in[1];
    const float* Whi = (const float*)d_in[2];
    const float* bi  = (const float*)d_in[3];
    const float* Wuf = (const float*)d_in[4];
    const float* Whf = (const float*)d_in[5];
    const float* bf  = (const float*)d_in[6];
    const float* Wug = (const float*)d_in[7];
    const float* Whg = (const float*)d_in[8];
    const float* bg  = (const float*)d_in[9];
    const float* Wuo = (const float*)d_in[10];
    const float* Who = (const float*)d_in[11];
    const float* bo  = (const float*)d_in[12];
    float* out = (float*)d_out;

    cudaFuncSetAttribute(lstm_mma,
                         cudaFuncAttributeMaxDynamicSharedMemorySize, DYN_BYTES);

    dim3 xu_grid(G4 / XBN, (SEQ * BATCH) / XBM);   // (32, 2048)
    xu_kernel<<<xu_grid, 256>>>(x, Wui, Wuf, Wug, Wuo, bi, bf, bg, bo);

    lstm_mma<<<128, 512, DYN_BYTES>>>(out, Whi, Whf, Whg, Who);
}

// round 15
// speedup vs baseline: 2.0300x; 1.0185x over previous
#include <cuda_runtime.h>
#include <cuda_bf16.h>
#include <math.h>
#include <stdint.h>

#define BATCH 256
#define SEQ   512
#define ISZ   256
#define HSZ   512
#define G4    2048   // 4*HSZ gate-interleaved: col j = u*4 + g, g in {i,f,g,o}

typedef unsigned long long ull;

// ---------------- device scratch (allocation-free) ----------------
__device__ float g_xu[(size_t)SEQ * BATCH * G4];       // xu[t][b][j] fp32
__device__ __nv_bfloat16 g_hh[2][BATCH * HSZ];         // h hi (bf16), double-buffered
__device__ __nv_bfloat16 g_hl[2][BATCH * HSZ];         // h lo (bf16), double-buffered
__device__ unsigned g_arr[256];                        // [4 mg][4 chunk] counters @ idx (mg*4+cc)*16

// ---------------- helpers ----------------
__device__ __forceinline__ ull fma2(ull a, ull b, ull c) {
    ull d;
    asm("fma.rn.f32x2 %0, %1, %2, %3;" : "=l"(d) : "l"(a), "l"(b), "l"(c));
    return d;
}
__device__ __forceinline__ float2 unpk(ull v) {
    float2 r;
    asm("mov.b64 {%0, %1}, %2;" : "=f"(r.x), "=f"(r.y) : "l"(v));
    return r;
}
__device__ __forceinline__ float fsig(float x)  { return 1.0f / (1.0f + __expf(-x)); }
__device__ __forceinline__ float ftanh(float x) { return 2.0f / (1.0f + __expf(-2.0f * x)) - 1.0f; }

__device__ __forceinline__ void arrive_release(unsigned* p) {
    asm volatile("red.release.gpu.global.add.u32 [%0], 1;" :: "l"(p) : "memory");
}
__device__ __forceinline__ unsigned poll_acquire(const unsigned* p) {
    unsigned v;
    asm volatile("ld.acquire.gpu.global.u32 %0, [%1];" : "=r"(v) : "l"(p) : "memory");
    return v;
}
__device__ __forceinline__ void wait_ctr(const unsigned* p, unsigned tgt) {
    while ((int)(poll_acquire(p) - tgt) < 0) { __nanosleep(32); }
}

// warp-level MMA primitives (baseline PTX, valid on compute_103)
__device__ __forceinline__ void ldmx4(uint32_t* r, uint32_t addr) {
    asm volatile("ldmatrix.sync.aligned.m8n8.x4.shared.b16 {%0,%1,%2,%3}, [%4];"
                 : "=r"(r[0]), "=r"(r[1]), "=r"(r[2]), "=r"(r[3]) : "r"(addr));
}
__device__ __forceinline__ void mma_bf16(float* c, const uint32_t* a, const uint32_t* b) {
    asm volatile(
        "mma.sync.aligned.m16n8k16.row.col.f32.bf16.bf16.f32 "
        "{%0,%1,%2,%3}, {%4,%5,%6,%7}, {%8,%9}, {%0,%1,%2,%3};"
        : "+f"(c[0]), "+f"(c[1]), "+f"(c[2]), "+f"(c[3])
        : "r"(a[0]), "r"(a[1]), "r"(a[2]), "r"(a[3]), "r"(b[0]), "r"(b[1]));
}
__device__ __forceinline__ void cpa16(uint32_t dst, const void* src) {
    asm volatile("cp.async.cg.shared.global [%0], [%1], 16;" :: "r"(dst), "l"(src));
}
__device__ __forceinline__ void cpa_commit_wait() {
    asm volatile("cp.async.commit_group;");
    asm volatile("cp.async.wait_group 0;" ::: "memory");
}

// ============ phase 1: xu = x @ Wu (interleaved on the fly) + bias ==========
#define XBM 64
#define XBN 64
#define XBK 16
#define XAS 34

__global__ __launch_bounds__(256) void xu_kernel(
    const float* __restrict__ x,
    const float* __restrict__ Wui, const float* __restrict__ Wuf,
    const float* __restrict__ Wug, const float* __restrict__ Wuo,
    const float* __restrict__ bi,  const float* __restrict__ bf,
    const float* __restrict__ bg,  const float* __restrict__ bo) {
    __shared__ float As[XBM * XAS];
    __shared__ float Bs[XBK * XBN];

    if (blockIdx.x == 0 && blockIdx.y == 0 && threadIdx.x < 16)
        g_arr[threadIdx.x * 16] = 0u;

    int m0 = blockIdx.y * XBM;
    int n0 = blockIdx.x * XBN;
    int tid = threadIdx.x;
    int tx = tid & 15;
    int ty = tid >> 4;

    int prow = tid >> 2;
    int pkof = (tid & 3) * 4;
    int brow = tid >> 4;
    int bu   = tid & 15;

    int m = m0 + prow;
    int t = m >> 8;
    int b = m & 255;
    const float* aptr = x + (size_t)b * (SEQ * ISZ) + (size_t)t * ISZ + pkof;
    int ubase = (n0 >> 2) + bu;

    ull acc[4][2] = {};

    for (int k0 = 0; k0 < ISZ; k0 += XBK) {
        float4 av = *(const float4*)(aptr + k0);
        *(float2*)&As[prow * XAS + 2 * (pkof + 0)] = make_float2(av.x, av.x);
        *(float2*)&As[prow * XAS + 2 * (pkof + 1)] = make_float2(av.y, av.y);
        *(float2*)&As[prow * XAS + 2 * (pkof + 2)] = make_float2(av.z, av.z);
        *(float2*)&As[prow * XAS + 2 * (pkof + 3)] = make_float2(av.w, av.w);
        int kr = (k0 + brow) * HSZ + ubase;
        Bs[brow * XBN + bu * 4 + 0] = Wui[kr];
        Bs[brow * XBN + bu * 4 + 1] = Wuf[kr];
        Bs[brow * XBN + bu * 4 + 2] = Wug[kr];
        Bs[brow * XBN + bu * 4 + 3] = Wuo[kr];
        __syncthreads();

#pragma unroll
        for (int kk = 0; kk < XBK; kk++) {
            ulonglong2 b2 = *(const ulonglong2*)&Bs[kk * XBN + tx * 4];
#pragma unroll
            for (int r = 0; r < 4; r++) {
                ull a2 = *(const ull*)&As[(ty * 4 + r) * XAS + 2 * kk];
                acc[r][0] = fma2(a2, b2.x, acc[r][0]);
                acc[r][1] = fma2(a2, b2.y, acc[r][1]);
            }
        }
        __syncthreads();
    }

    int u = (n0 >> 2) + tx;
    float4 bias = {bi[u], bf[u], bg[u], bo[u]};
#pragma unroll
    for (int r = 0; r < 4; r++) {
        float2 lo = unpk(acc[r][0]);
        float2 hi = unpk(acc[r][1]);
        float4 ov = {lo.x + bias.x, lo.y + bias.y, hi.x + bias.z, hi.y + bias.w};
        *(float4*)(g_xu + (size_t)(m0 + ty * 4 + r) * G4 + n0 + tx * 4) = ov;
    }
}

// ============ phase 2: PERSISTENT mma.sync, dataflow sub-barriers ============
// 128 CTAs = 4 M-groups x 32 n-tiles; CTA tile C[64 batch][64 gate-cols].
// 512 threads: warps 0-7 = MMA (2M x 4N, warp tile 32x16, m16n8k16 bf16,
// fp32 accum, bf16 hi/lo x3 split, frag double-buffered); warps 8-15 =
// cp.async producers gated by per-chunk counters (chunk cc <- the 8 CTAs
// owning units [cc*128, cc*128+128)). h double-buffered in global.
#define W_STRIDE_B 1040
#define A_STRIDE_B 272
#define A_OFF      133120u
#define A_ARR_B    17408u
#define A_BUF_B    34816u
#define CS_OFF     202752u
#define CS_STRIDE  68
#define DYN_BYTES  (220160 + 1024)

__global__ __launch_bounds__(512, 1)
void lstm_mma(float* __restrict__ out,
              const float* __restrict__ Whi, const float* __restrict__ Whf,
              const float* __restrict__ Whg, const float* __restrict__ Who) {
    extern __shared__ char s8[];
    uint32_t raw;
    asm("{ .reg .u64 t; cvta.to.shared.u64 t, %1; cvt.u32.u64 %0, t; }"
        : "=r"(raw) : "l"(s8));
    uint32_t base = (raw + 1023) & ~1023u;
    char* dynb = s8 + (base - raw);
    float* CS = (float*)(dynb + CS_OFF);

    int tid = threadIdx.x;
    int l = tid & 31;
    int warp = tid >> 5;
    int is_mma = (warp < 8);
    int wm = warp & 1;           // M warp (32 rows)  [mma warps]
    int wn = (warp >> 1) & 3;    // N warp (16 cols)

    int nt = blockIdx.x & 31;    // n-tile (64 gate cols = 16 units)
    int mg = blockIdx.x >> 5;    // M-group 0..3
    int ncol0 = nt * 64;         // xu col base
    int u0 = nt * 16;
    int b0 = mg * 64;
    unsigned* my_ctr = &g_arr[(mg * 4 + (nt >> 3)) * 16];   // this CTA's chunk counter

    // ---- one-time: W_h slice -> bf16 hi/lo, padded [n][k] ----
    for (int e = tid; e < 64 * 512; e += 512) {
        int n = e >> 9, k = e & 511;
        int u = u0 + (n >> 2), g = n & 3;
        const float* W = (g == 0) ? Whi : (g == 1) ? Whf : (g == 2) ? Whg : Who;
        float w = W[k * HSZ + u];
        __nv_bfloat16 hi = __float2bfloat16(w);
        __nv_bfloat16 lo = __float2bfloat16(w - __bfloat162float(hi));
        *(__nv_bfloat16*)(dynb + n * W_STRIDE_B + k * 2) = hi;
        *(__nv_bfloat16*)(dynb + 66560 + n * W_STRIDE_B + k * 2) = lo;
    }
    __syncthreads();

    // ldmatrix lane address components (mma warps)
    int amrow = (l & 7) + ((l >> 3) & 1) * 8;          // 0..15
    int acolb = ((l >> 4) * 8) * 2;                     // 0 or 16 bytes
    uint32_t aoff0 = (uint32_t)(wm * 32 + amrow) * A_STRIDE_B + acolb;
    uint32_t aoff1 = aoff0 + 16u * A_STRIDE_B;
    int bnrow = wn * 16 + (l & 7) + ((l >> 4) & 1) * 8;
    int bkclb = (((l >> 3) & 1) * 8) * 2;
    uint32_t boff_hi = base + (uint32_t)bnrow * W_STRIDE_B + bkclb;
    uint32_t boff_lo = boff_hi + 66560u;

    // producer staging (warps 8-15): ptid 0..255 -> (row 0..63, arr, half)
    int ptid = tid - 256;
    int srow = ptid & 63;
    int sarr = (ptid >> 6) & 1;
    int shalf = (ptid >> 7) & 1;
    uint32_t sdst = base + A_OFF + (uint32_t)sarr * A_ARR_B
                  + (uint32_t)srow * A_STRIDE_B + (uint32_t)shalf * 128u;

    // epilogue mapping: 512 threads, 1 row x 2 units (8 gates) each
    int erow = tid >> 3;         // 0..63
    int eq   = tid & 7;          // col-oct

    float c2[2] = {0.f, 0.f};
    float cacc[2][2][4];

    for (int t = 0; t < SEQ; t++) {
        // prefetch this thread's xu gates at step top (overlaps whole GEMM)
        const float* xp = g_xu + ((size_t)t * BATCH + b0 + erow) * G4 + ncol0 + eq * 8;
        float4 xv0 = __ldcg((const float4*)xp);
        float4 xv1 = __ldcg((const float4*)(xp + 4));

        int rbuf = (t & 1) ^ 1;                      // h[t-1] buffer
        const __nv_bfloat16* hsrc =
            (sarr ? g_hl[rbuf] : g_hh[rbuf]) + (size_t)(b0 + srow) * HSZ + shalf * 64;

        if (t > 0) {
            if (is_mma) {
#pragma unroll
                for (int mt = 0; mt < 2; mt++)
#pragma unroll
                    for (int ntl = 0; ntl < 2; ntl++)
#pragma unroll
                        for (int j = 0; j < 4; j++) cacc[mt][ntl][j] = 0.f;
            } else {
                // producers: wait for chunk-0 owners, then stage chunk 0 -> buf 0
                wait_ctr(&g_arr[(mg * 4 + 0) * 16], (unsigned)t * 8u);
#pragma unroll
                for (int j = 0; j < 8; j++)
                    cpa16(sdst + j * 16, hsrc + j * 8);
                cpa_commit_wait();
            }
            __syncthreads();

            for (int cc = 0; cc < 4; cc++) {
                if (is_mma) {
                    uint32_t abh = base + A_OFF + (uint32_t)(cc & 1) * A_BUF_B;
                    uint32_t abl = abh + A_ARR_B;
                    uint32_t fA[2][4][4];
                    uint32_t fB[2][2][4];
#define LD_FR(bi_, ks_) do { \
                    uint32_t ka_ = (uint32_t)((ks_) * 32); \
                    uint32_t kb_ = (uint32_t)(cc * 256 + (ks_) * 32); \
                    ldmx4(fA[bi_][0], abh + aoff0 + ka_); \
                    ldmx4(fA[bi_][1], abh + aoff1 + ka_); \
                    ldmx4(fA[bi_][2], abl + aoff0 + ka_); \
                    ldmx4(fA[bi_][3], abl + aoff1 + ka_); \
                    ldmx4(fB[bi_][0], boff_hi + kb_); \
                    ldmx4(fB[bi_][1], boff_lo + kb_); } while (0)
                    LD_FR(0, 0);
#pragma unroll
                    for (int ks = 0; ks < 8; ks++) {
                        const int cur = ks & 1;
                        if (ks < 7) LD_FR(cur ^ 1, ks + 1);
                        // hi*hi
                        mma_bf16(cacc[0][0], fA[cur][0], fB[cur][0] + 0);
                        mma_bf16(cacc[0][1], fA[cur][0], fB[cur][0] + 2);
                        mma_bf16(cacc[1][0], fA[cur][1], fB[cur][0] + 0);
                        mma_bf16(cacc[1][1], fA[cur][1], fB[cur][0] + 2);
                        // hi*lo
                        mma_bf16(cacc[0][0], fA[cur][0], fB[cur][1] + 0);
                        mma_bf16(cacc[0][1], fA[cur][0], fB[cur][1] + 2);
                        mma_bf16(cacc[1][0], fA[cur][1], fB[cur][1] + 0);
                        mma_bf16(cacc[1][1], fA[cur][1], fB[cur][1] + 2);
                        // lo*hi
                        mma_bf16(cacc[0][0], fA[cur][2], fB[cur][0] + 0);
                        mma_bf16(cacc[0][1], fA[cur][2], fB[cur][0] + 2);
                        mma_bf16(cacc[1][0], fA[cur][3], fB[cur][0] + 0);
                        mma_bf16(cacc[1][1], fA[cur][3], fB[cur][0] + 2);
                    }
#undef LD_FR
                } else if (cc < 3) {
                    // producers: wait for chunk cc+1 owners, stage -> buf (cc+1)&1
                    wait_ctr(&g_arr[(mg * 4 + cc + 1) * 16], (unsigned)t * 8u);
                    const __nv_bfloat16* gs = hsrc + (cc + 1) * 128;
                    uint32_t dn = sdst + (uint32_t)((cc + 1) & 1) * A_BUF_B;
#pragma unroll
                    for (int j = 0; j < 8; j++)
                        cpa16(dn + j * 16, gs + j * 8);
                    cpa_commit_wait();
                }
                __syncthreads();
            }

            // ---- C frags -> smem (mma warps only) ----
            if (is_mma) {
                int crow = wm * 32 + (l >> 2);
                int ccol = wn * 16 + 2 * (l & 3);
#pragma unroll
                for (int mt = 0; mt < 2; mt++)
#pragma unroll
                    for (int ntl = 0; ntl < 2; ntl++) {
                        int r = crow + mt * 16;
                        int cl = ccol + ntl * 8;
                        *(float2*)&CS[r * CS_STRIDE + cl] =
                            make_float2(cacc[mt][ntl][0], cacc[mt][ntl][1]);
                        *(float2*)&CS[(r + 8) * CS_STRIDE + cl] =
                            make_float2(cacc[mt][ntl][2], cacc[mt][ntl][3]);
                    }
            }
            __syncthreads();
        }

        // ---- fused LSTM epilogue: 512 threads, 1 row x 2 units each ----
        const float* cp = &CS[erow * CS_STRIDE + eq * 8];
        __align__(4) __nv_bfloat16 hh2[2], hl2[2];
        float hf2[2];
#pragma unroll
        for (int j = 0; j < 2; j++) {
            float4 xv = (j == 0) ? xv0 : xv1;
            float di = 0.f, df = 0.f, dg = 0.f, do_ = 0.f;
            if (t > 0) {
                float4 dv = *(const float4*)(cp + j * 4);
                di = dv.x; df = dv.y; dg = dv.z; do_ = dv.w;
            }
            float it = fsig(di + xv.x);
            float ft = fsig(df + xv.y);
            float gt = ftanh(dg + xv.z);
            float ot = fsig(do_ + xv.w);
            c2[j] = ft * c2[j] + it * gt;
            float h = ot * ftanh(c2[j]);
            hf2[j] = h;
            __nv_bfloat16 hb = __float2bfloat16(h);
            hh2[j] = hb;
            hl2[j] = __float2bfloat16(h - __bfloat162float(hb));
        }
        size_t ho = (size_t)(b0 + erow) * HSZ + u0 + eq * 2;
        if (t == SEQ - 1) {
            *(float2*)(out + ho) = make_float2(hf2[0], hf2[1]);
        } else {
            int wb = t & 1;
            *(uint32_t*)(g_hh[wb] + ho) = *(uint32_t*)hh2;
            *(uint32_t*)(g_hl[wb] + ho) = *(uint32_t*)hl2;
        }

        // ---- dataflow arrival: publish this CTA's h-units for step t ----
        if (t < SEQ - 1) {
            __syncthreads();
            if (tid == 0) arrive_release(my_ctr);
        }
    }
}

// ---------------- launch ----------------------------------------------------
extern "C" void kernel_launch(void* const* d_in, const int* in_sizes, int n_in,
                              void* d_out, int out_size) {
    const float* x   = (const float*)d_in[0];
    const float* Wui = (const float*)d_in[1];
    const float* Whi = (const float*)d_in[2];
    const float* bi  = (const float*)d_in[3];
    const float* Wuf = (const float*)d_in[4];
    const float* Whf = (const float*)d_in[5];
    const float* bf  = (const float*)d_in[6];
    const float* Wug = (const float*)d_in[7];
    const float* Whg = (const float*)d_in[8];
    const float* bg  = (const float*)d_in[9];
    const float* Wuo = (const float*)d_in[10];
    const float* Who = (const float*)d_in[11];
    const float* bo  = (const float*)d_in[12];
    float* out = (float*)d_out;

    cudaFuncSetAttribute(lstm_mma,
                         cudaFuncAttributeMaxDynamicSharedMemorySize, DYN_BYTES);

    dim3 xu_grid(G4 / XBN, (SEQ * BATCH) / XBM);   // (32, 2048)
    xu_kernel<<<xu_grid, 256>>>(x, Wui, Wuf, Wug, Wuo, bi, bf, bg, bo);

    lstm_mma<<<128, 512, DYN_BYTES>>>(out, Whi, Whf, Whg, Who);
}